// round 12
// baseline (speedup 1.0000x reference)
#include <cuda_runtime.h>
#include <math.h>
#include <stdint.h>

// Problem constants (B=2, S=1024, H=2048, I=1408, E=8, TOP_K=2)
#define T_TOK 2048
#define H_DIM 2048
#define I_DIM 1408
#define E_NUM 8
#define GU_W  (2*I_DIM)   // 2816

// ---------------- scratch (device globals; no allocations allowed) ----------
__device__ int   g_counts[E_NUM];
__device__ int   g_tok [E_NUM*T_TOK];
__device__ float g_wgt [E_NUM*T_TOK];
__device__ int   g_slot[E_NUM*T_TOK];
__device__ __align__(16) float g_gu[(size_t)E_NUM*T_TOK*GU_W];        // ~184 MB
__device__ __align__(16) float g_slotout[2ull*T_TOK*H_DIM];           // ~33 MB

// ---------------- PTX helpers ----------------------------------------------
__device__ __forceinline__ uint32_t cvta_smem(const void* p) {
    uint32_t r;
    asm("{ .reg .u64 t; cvta.to.shared.u64 t, %1; cvt.u32.u64 %0, t; }"
        : "=r"(r) : "l"(p));
    return r;
}
__device__ __forceinline__ void ldsm4(uint32_t* r, uint32_t addr) {
    asm volatile("ldmatrix.sync.aligned.m8n8.x4.shared.b16 {%0,%1,%2,%3}, [%4];"
        : "=r"(r[0]), "=r"(r[1]), "=r"(r[2]), "=r"(r[3]) : "r"(addr));
}
__device__ __forceinline__ void mma_tf32(float* c, const uint32_t* a, const uint32_t* b) {
    asm volatile(
        "mma.sync.aligned.m16n8k8.row.col.f32.tf32.tf32.f32 "
        "{%0,%1,%2,%3}, {%4,%5,%6,%7}, {%8,%9}, {%0,%1,%2,%3};"
        : "+f"(c[0]), "+f"(c[1]), "+f"(c[2]), "+f"(c[3])
        : "r"(a[0]), "r"(a[1]), "r"(a[2]), "r"(a[3]), "r"(b[0]), "r"(b[1]));
}
__device__ __forceinline__ uint32_t f2tf32(float v) {
    uint32_t r; asm("cvt.rna.tf32.f32 %0, %1;" : "=r"(r) : "f"(v)); return r;
}

// smem: 3-stage ring; each stage 64KB = Ahi(16K) Alo(16K) Bhi(16K) Blo(16K)
#define TILE_B   16384
#define STAGE_B  (4*TILE_B)               // 65536
#define SMEM_DYN (1024 + 3*STAGE_B)       // ~193KB

// ---------------- kernel 0: zero counters ----------------------------------
__global__ void zero_counts_kernel() {
    if (threadIdx.x < E_NUM) g_counts[threadIdx.x] = 0;
}

// ---------------- kernel 1: gating ------------------------------------------
__global__ void gate_kernel(const float* __restrict__ x,
                            const float* __restrict__ gw) {
    const int t = blockIdx.x;
    const float* xr = x + (size_t)t * H_DIM;
    float acc[E_NUM];
#pragma unroll
    for (int e = 0; e < E_NUM; e++) acc[e] = 0.f;
    for (int h = threadIdx.x; h < H_DIM; h += blockDim.x) {
        float xv = xr[h];
#pragma unroll
        for (int e = 0; e < E_NUM; e++) acc[e] += xv * gw[e * H_DIM + h];
    }
    __shared__ float s_part[E_NUM][8];
    __shared__ float s_logit[E_NUM];
    const int lane = threadIdx.x & 31, warp = threadIdx.x >> 5;
#pragma unroll
    for (int off = 16; off > 0; off >>= 1)
#pragma unroll
        for (int e = 0; e < E_NUM; e++)
            acc[e] += __shfl_down_sync(0xffffffffu, acc[e], off);
    if (lane == 0)
#pragma unroll
        for (int e = 0; e < E_NUM; e++) s_part[e][warp] = acc[e];
    __syncthreads();
    if (threadIdx.x < E_NUM) {
        float s = 0.f;
#pragma unroll
        for (int w = 0; w < 8; w++) s += s_part[threadIdx.x][w];
        s_logit[threadIdx.x] = s;
    }
    __syncthreads();
    if (threadIdx.x == 0) {
        float lg[E_NUM];
#pragma unroll
        for (int e = 0; e < E_NUM; e++) lg[e] = s_logit[e];
        float mx = lg[0];
#pragma unroll
        for (int e = 1; e < E_NUM; e++) mx = fmaxf(mx, lg[e]);
        float pe[E_NUM], se = 0.f;
#pragma unroll
        for (int e = 0; e < E_NUM; e++) { pe[e] = expf(lg[e] - mx); se += pe[e]; }
#pragma unroll
        for (int e = 0; e < E_NUM; e++) pe[e] /= se;
        int b0 = 0;
#pragma unroll
        for (int e = 1; e < E_NUM; e++) if (pe[e] > pe[b0]) b0 = e;
        int b1 = -1;
#pragma unroll
        for (int e = 0; e < E_NUM; e++)
            if (e != b0 && (b1 < 0 || pe[e] > pe[b1])) b1 = e;
        float s2 = pe[b0] + pe[b1];
        int p0 = atomicAdd(&g_counts[b0], 1);
        g_tok [b0 * T_TOK + p0] = t; g_wgt[b0 * T_TOK + p0] = pe[b0] / s2;
        g_slot[b0 * T_TOK + p0] = 0;
        int p1 = atomicAdd(&g_counts[b1], 1);
        g_tok [b1 * T_TOK + p1] = t; g_wgt[b1 * T_TOK + p1] = pe[b1] / s2;
        g_slot[b1 * T_TOK + p1] = 1;
    }
}

// ---- split 8 float4 and store to hi/lo tiles of buffer `bi` ----------------
#define STS_SPLIT(bi, regs)                                                    \
    do {                                                                       \
        const uint32_t _hb = hbase + (uint32_t)(bi) * STAGE_B;                 \
        const uint32_t _lb = _hb + TILE_B;                                     \
        _Pragma("unroll")                                                      \
        for (int c = 0; c < 8; c++) {                                          \
            float4 v = (regs)[c];                                              \
            uint32_t hx = f2tf32(v.x), hy = f2tf32(v.y),                       \
                     hz = f2tf32(v.z), hw = f2tf32(v.w);                       \
            uint32_t lx = f2tf32(v.x - __uint_as_float(hx));                   \
            uint32_t ly = f2tf32(v.y - __uint_as_float(hy));                   \
            uint32_t lz = f2tf32(v.z - __uint_as_float(hz));                   \
            uint32_t lw = f2tf32(v.w - __uint_as_float(hw));                   \
            asm volatile("st.shared.v4.b32 [%0], {%1,%2,%3,%4};"               \
                :: "r"(_hb + soff[c]), "r"(hx), "r"(hy), "r"(hz), "r"(hw) : "memory"); \
            asm volatile("st.shared.v4.b32 [%0], {%1,%2,%3,%4};"               \
                :: "r"(_lb + soff[c]), "r"(lx), "r"(ly), "r"(lz), "r"(lw) : "memory"); \
        }                                                                      \
    } while (0)

// ======== pre-split 3xTF32 mainloop: 3-stage ring, 1 barrier/slab, ==========
// ======== sweep-ordered MMAs (16 independent per sweep, 3 sweeps)  ==========
#define GEMM_MAINLOOP(SRC_PTR, KT)                                             \
    const int row = tid & 127;                                                 \
    const uint32_t hbase = tb + ((tid < 128) ? 0 : 2 * TILE_B);                \
    uint32_t soff[8];                                                          \
    _Pragma("unroll")                                                          \
    for (int c = 0; c < 8; c++)                                                \
        soff[c] = (uint32_t)(row * 128) + (uint32_t)((c ^ (row & 7)) << 4);    \
    float4 cur[8], nxt[8];                                                     \
    {   /* prologue: slab0 -> buf0, slab1 -> regs */                           \
        const float* s0 = (SRC_PTR);                                           \
        _Pragma("unroll")                                                      \
        for (int c = 0; c < 8; c++) cur[c] = *(const float4*)(s0 + c * 4);     \
        STS_SPLIT(0, cur);                                                     \
        const float* s1 = (SRC_PTR) + 32;                                      \
        _Pragma("unroll")                                                      \
        for (int c = 0; c < 8; c++) cur[c] = *(const float4*)(s1 + c * 4);     \
    }                                                                          \
    for (int k = 0; k < (KT); k++) {                                           \
        const int kb = k - (k / 3) * 3;          /* k % 3 */                   \
        if (k + 1 < (KT)) {                                                    \
            const int nb = (kb == 2) ? 0 : kb + 1;                             \
            STS_SPLIT(nb, cur);                                                \
        }                                                                      \
        if (k + 2 < (KT)) {                                                    \
            const float* sn = (SRC_PTR) + (k + 2) * 32;                        \
            _Pragma("unroll")                                                  \
            for (int c = 0; c < 8; c++) nxt[c] = *(const float4*)(sn + c * 4); \
        }                                                                      \
        __syncthreads();                                                       \
        const uint32_t Sb = tb + (uint32_t)kb * STAGE_B;                       \
        const uint32_t Ah = Sb,              Al = Sb + TILE_B;                 \
        const uint32_t Bh = Sb + 2 * TILE_B, Bl = Sb + 3 * TILE_B;             \
        _Pragma("unroll")                                                      \
        for (int s = 0; s < 4; s++) {                                          \
            uint32_t afh[4][4], afl[4][4], bfh[4][2], bfl[4][2];               \
            _Pragma("unroll")                                                  \
            for (int mt = 0; mt < 4; mt++) {                                   \
                const uint32_t ro = aRow[mt] * 128 +                           \
                    (((2 * s + agsel) ^ (aRow[mt] & 7)) << 4);                 \
                ldsm4(afh[mt], Ah + ro);                                       \
                ldsm4(afl[mt], Al + ro);                                       \
            }                                                                  \
            _Pragma("unroll")                                                  \
            for (int p = 0; p < 2; p++) {                                      \
                const uint32_t ro = bRow[p] * 128 +                            \
                    (((2 * s + bgsel) ^ (bRow[p] & 7)) << 4);                  \
                uint32_t rh[4], rl[4];                                         \
                ldsm4(rh, Bh + ro);                                            \
                ldsm4(rl, Bl + ro);                                            \
                bfh[2*p][0] = rh[0]; bfh[2*p][1] = rh[1];                      \
                bfh[2*p+1][0] = rh[2]; bfh[2*p+1][1] = rh[3];                  \
                bfl[2*p][0] = rl[0]; bfl[2*p][1] = rl[1];                      \
                bfl[2*p+1][0] = rl[2]; bfl[2*p+1][1] = rl[3];                  \
            }                                                                  \
            /* sweep 1: hi*lo  (16 independent accumulators) */                \
            _Pragma("unroll")                                                  \
            for (int mt = 0; mt < 4; mt++)                                     \
                _Pragma("unroll")                                              \
                for (int nt = 0; nt < 4; nt++)                                 \
                    mma_tf32(acc[mt][nt], afh[mt], bfl[nt]);                   \
            /* sweep 2: lo*hi */                                               \
            _Pragma("unroll")                                                  \
            for (int mt = 0; mt < 4; mt++)                                     \
                _Pragma("unroll")                                              \
                for (int nt = 0; nt < 4; nt++)                                 \
                    mma_tf32(acc[mt][nt], afl[mt], bfh[nt]);                   \
            /* sweep 3: hi*hi */                                               \
            _Pragma("unroll")                                                  \
            for (int mt = 0; mt < 4; mt++)                                     \
                _Pragma("unroll")                                              \
                for (int nt = 0; nt < 4; nt++)                                 \
                    mma_tf32(acc[mt][nt], afh[mt], bfh[nt]);                   \
        }                                                                      \
        _Pragma("unroll")                                                      \
        for (int c = 0; c < 8; c++) cur[c] = nxt[c];                           \
    }

// ---------------- GEMM1: gu[rows, 2816] = x[tok] * w1[e]^T  (K=2048) --------
__global__ __launch_bounds__(256, 1)
void gemm1_kernel(const float* __restrict__ x, const float* __restrict__ w1) {
    const int e    = blockIdx.z;
    const int rows = g_counts[e];
    const int m0   = blockIdx.x * 128;
    if (m0 >= rows) return;
    const int n0   = blockIdx.y * 128;

    extern __shared__ __align__(16) char smem[];
    const uint32_t sb = cvta_smem(smem);
    const uint32_t tb = (sb + 1023u) & ~1023u;
    const int tid = threadIdx.x, lane = tid & 31, wid = tid >> 5;
    const int wm = wid & 1, wn = wid >> 1;

    const int grp = lane >> 3, r8 = lane & 7;
    const int agsel = grp >> 1, bgsel = grp & 1;
    int aRow[4], bRow[2];
#pragma unroll
    for (int mt = 0; mt < 4; mt++) aRow[mt] = wm * 64 + mt * 16 + ((grp & 1) << 3) + r8;
#pragma unroll
    for (int p = 0; p < 2; p++)    bRow[p]  = wn * 32 + p * 16 + ((grp >> 1) << 3) + r8;

    float acc[4][4][4];
#pragma unroll
    for (int i = 0; i < 4; i++)
#pragma unroll
        for (int j = 0; j < 4; j++)
#pragma unroll
            for (int q = 0; q < 4; q++) acc[i][j][q] = 0.f;

    const float* src;
    if (tid < 128) {
        const int mi = m0 + (tid & 127);
        const int tok = (mi < rows) ? g_tok[e * T_TOK + mi] : 0;
        src = x + (size_t)tok * H_DIM;
    } else {
        src = w1 + (size_t)e * GU_W * H_DIM + (size_t)(n0 + (tid & 127)) * H_DIM;
    }

    GEMM_MAINLOOP(src, (H_DIM / 32))

    const int lr = lane >> 2, lc = (lane & 3) * 2;
    const int mb = m0 + wm * 64, nb = n0 + wn * 32;
#pragma unroll
    for (int mt = 0; mt < 4; mt++) {
#pragma unroll
        for (int half = 0; half < 2; half++) {
            const int orow = mb + mt * 16 + half * 8 + lr;
            if (orow < rows) {
                float* dst = g_gu + (size_t)(e * T_TOK + orow) * GU_W + nb + lc;
#pragma unroll
                for (int nt = 0; nt < 4; nt++) {
                    float2 v = make_float2(acc[mt][nt][2 * half], acc[mt][nt][2 * half + 1]);
                    *(float2*)(dst + nt * 8) = v;
                }
            }
        }
    }
}

// ---------------- kernel 3: act = silu(g) * u (in place) --------------------
__global__ void act_kernel() {
    const int r = blockIdx.x;
    const int e = r / T_TOK, pos = r % T_TOK;
    if (pos >= g_counts[e]) return;
    float* gu = g_gu + (size_t)r * GU_W;
    for (int i = threadIdx.x * 4; i < I_DIM; i += blockDim.x * 4) {
        float4 g4 = *(const float4*)(gu + i);
        float4 u4 = *(const float4*)(gu + I_DIM + i);
        float4 o;
        o.x = (g4.x / (1.f + expf(-g4.x))) * u4.x;
        o.y = (g4.y / (1.f + expf(-g4.y))) * u4.y;
        o.z = (g4.z / (1.f + expf(-g4.z))) * u4.z;
        o.w = (g4.w / (1.f + expf(-g4.w))) * u4.w;
        *(float4*)(gu + i) = o;
    }
}

// ---------------- GEMM2: slot_out = wgt * (act * w2[e]^T)  (K=1408) ---------
__global__ __launch_bounds__(256, 1)
void gemm2_kernel(const float* __restrict__ w2) {
    const int e    = blockIdx.z;
    const int rows = g_counts[e];
    const int m0   = blockIdx.x * 128;
    if (m0 >= rows) return;
    const int n0   = blockIdx.y * 128;

    extern __shared__ __align__(16) char smem[];
    const uint32_t sb = cvta_smem(smem);
    const uint32_t tb = (sb + 1023u) & ~1023u;
    const int tid = threadIdx.x, lane = tid & 31, wid = tid >> 5;
    const int wm = wid & 1, wn = wid >> 1;

    const int grp = lane >> 3, r8 = lane & 7;
    const int agsel = grp >> 1, bgsel = grp & 1;
    int aRow[4], bRow[2];
#pragma unroll
    for (int mt = 0; mt < 4; mt++) aRow[mt] = wm * 64 + mt * 16 + ((grp & 1) << 3) + r8;
#pragma unroll
    for (int p = 0; p < 2; p++)    bRow[p]  = wn * 32 + p * 16 + ((grp >> 1) << 3) + r8;

    float acc[4][4][4];
#pragma unroll
    for (int i = 0; i < 4; i++)
#pragma unroll
        for (int j = 0; j < 4; j++)
#pragma unroll
            for (int q = 0; q < 4; q++) acc[i][j][q] = 0.f;

    const float* src;
    if (tid < 128) {
        const int mi = m0 + (tid & 127);
        const int rr = (mi < rows) ? mi : 0;
        src = g_gu + (size_t)(e * T_TOK + rr) * GU_W;
    } else {
        src = w2 + (size_t)e * H_DIM * I_DIM + (size_t)(n0 + (tid & 127)) * I_DIM;
    }

    GEMM_MAINLOOP(src, (I_DIM / 32))

    const int lr = lane >> 2, lc = (lane & 3) * 2;
    const int mb = m0 + wm * 64, nbase = n0 + wn * 32;
#pragma unroll
    for (int mt = 0; mt < 4; mt++) {
#pragma unroll
        for (int half = 0; half < 2; half++) {
            const int orow = mb + mt * 16 + half * 8 + lr;
            if (orow < rows) {
                const int li = e * T_TOK + orow;
                const float w = g_wgt[li];
                const int tok = g_tok[li];
                const int slot = g_slot[li];
                float* dst = g_slotout + (size_t)slot * T_TOK * H_DIM
                                       + (size_t)tok * H_DIM + nbase + lc;
#pragma unroll
                for (int nt = 0; nt < 4; nt++) {
                    float2 v = make_float2(w * acc[mt][nt][2 * half],
                                           w * acc[mt][nt][2 * half + 1]);
                    *(float2*)(dst + nt * 8) = v;
                }
            }
        }
    }
}

// ---------------- kernel 5: combine slot0 + slot1 -> out --------------------
__global__ void combine_kernel(float* __restrict__ out) {
    const size_t idx4 = (size_t)blockIdx.x * blockDim.x + threadIdx.x;
    const size_t n4   = (size_t)T_TOK * H_DIM / 4;
    if (idx4 >= n4) return;
    float4 a = *((const float4*)g_slotout + idx4);
    float4 b = *((const float4*)g_slotout + n4 + idx4);
    float4 r; r.x = a.x + b.x; r.y = a.y + b.y; r.z = a.z + b.z; r.w = a.w + b.w;
    *((float4*)out + idx4) = r;
}

// ---------------- launch ----------------------------------------------------
extern "C" void kernel_launch(void* const* d_in, const int* in_sizes, int n_in,
                              void* d_out, int out_size) {
    const float* x  = (const float*)d_in[0];
    const float* gw = (const float*)d_in[1];
    const float* w1 = (const float*)d_in[2];
    const float* w2 = (const float*)d_in[3];
    float* out = (float*)d_out;

    cudaFuncSetAttribute(gemm1_kernel, cudaFuncAttributeMaxDynamicSharedMemorySize, SMEM_DYN);
    cudaFuncSetAttribute(gemm2_kernel, cudaFuncAttributeMaxDynamicSharedMemorySize, SMEM_DYN);

    zero_counts_kernel<<<1, 32>>>();
    gate_kernel<<<T_TOK, 256>>>(x, gw);

    dim3 g1(T_TOK / 128, GU_W / 128, E_NUM);   // (16, 22, 8)
    gemm1_kernel<<<g1, 256, SMEM_DYN>>>(x, w1);

    act_kernel<<<E_NUM * T_TOK, 128>>>();

    dim3 g2(T_TOK / 128, H_DIM / 128, E_NUM);  // (16, 16, 8)
    gemm2_kernel<<<g2, 256, SMEM_DYN>>>(w2);

    combine_kernel<<<(T_TOK * H_DIM / 4 + 255) / 256, 256>>>(out);
}

// round 14
// speedup vs baseline: 1.5405x; 1.5405x over previous
#include <cuda_runtime.h>
#include <cuda_fp16.h>
#include <math.h>
#include <stdint.h>

// Problem constants (B=2, S=1024, H=2048, I=1408, E=8, TOP_K=2)
#define T_TOK 2048
#define H_DIM 2048
#define I_DIM 1408
#define E_NUM 8
#define GU_W  (2*I_DIM)   // 2816

// ---------------- scratch (device globals; no allocations allowed) ----------
__device__ int   g_counts[E_NUM];
__device__ int   g_tok [E_NUM*T_TOK];
__device__ float g_wgt [E_NUM*T_TOK];
__device__ int   g_slot[E_NUM*T_TOK];
__device__ __align__(16) float g_gu[(size_t)E_NUM*T_TOK*GU_W];        // ~184 MB
__device__ __align__(16) float g_slotout[2ull*T_TOK*H_DIM];           // ~33 MB

// ---------------- PTX helpers ----------------------------------------------
__device__ __forceinline__ uint32_t cvta_smem(const void* p) {
    uint32_t r;
    asm("{ .reg .u64 t; cvta.to.shared.u64 t, %1; cvt.u32.u64 %0, t; }"
        : "=r"(r) : "l"(p));
    return r;
}
__device__ __forceinline__ void ldsm4(uint32_t* r, uint32_t addr) {
    asm volatile("ldmatrix.sync.aligned.m8n8.x4.shared.b16 {%0,%1,%2,%3}, [%4];"
        : "=r"(r[0]), "=r"(r[1]), "=r"(r[2]), "=r"(r[3]) : "r"(addr));
}
// fp16 MMA m16n8k16, fp32 accumulate
__device__ __forceinline__ void mma_f16(float* c, const uint32_t* a, const uint32_t* b) {
    asm volatile(
        "mma.sync.aligned.m16n8k16.row.col.f32.f16.f16.f32 "
        "{%0,%1,%2,%3}, {%4,%5,%6,%7}, {%8,%9}, {%0,%1,%2,%3};"
        : "+f"(c[0]), "+f"(c[1]), "+f"(c[2]), "+f"(c[3])
        : "r"(a[0]), "r"(a[1]), "r"(a[2]), "r"(a[3]), "r"(b[0]), "r"(b[1]));
}
// fp16 split: v = hi + lo (+O(2^-22))
__device__ __forceinline__ void split_f16(float v, __half& hi, __half& lo) {
    hi = __float2half_rn(v);
    lo = __float2half_rn(v - __half2float(hi));
}
__device__ __forceinline__ uint32_t pack2(__half a, __half b) {
    __half2 h = __halves2half2(a, b);
    return *(uint32_t*)&h;
}

// smem: 3-stage ring; each stage 32KB = A(16K: hi|lo per row) + B(16K)
// Row layout: 128 bytes = [32 fp16 hi | 32 fp16 lo], 8 chunks of 16B,
// chunk swizzle c ^= (row & 7)  (same proven pattern as fp32 version).
#define ATILE_B  16384
#define STAGE_B  32768
#define SMEM_DYN (1024 + 3*STAGE_B)   // ~97KB

// ---------------- kernel 0: zero counters ----------------------------------
__global__ void zero_counts_kernel() {
    if (threadIdx.x < E_NUM) g_counts[threadIdx.x] = 0;
}

// ---------------- kernel 1: gating ------------------------------------------
__global__ void gate_kernel(const float* __restrict__ x,
                            const float* __restrict__ gw) {
    const int t = blockIdx.x;
    const float* xr = x + (size_t)t * H_DIM;
    float acc[E_NUM];
#pragma unroll
    for (int e = 0; e < E_NUM; e++) acc[e] = 0.f;
    for (int h = threadIdx.x; h < H_DIM; h += blockDim.x) {
        float xv = xr[h];
#pragma unroll
        for (int e = 0; e < E_NUM; e++) acc[e] += xv * gw[e * H_DIM + h];
    }
    __shared__ float s_part[E_NUM][8];
    __shared__ float s_logit[E_NUM];
    const int lane = threadIdx.x & 31, warp = threadIdx.x >> 5;
#pragma unroll
    for (int off = 16; off > 0; off >>= 1)
#pragma unroll
        for (int e = 0; e < E_NUM; e++)
            acc[e] += __shfl_down_sync(0xffffffffu, acc[e], off);
    if (lane == 0)
#pragma unroll
        for (int e = 0; e < E_NUM; e++) s_part[e][warp] = acc[e];
    __syncthreads();
    if (threadIdx.x < E_NUM) {
        float s = 0.f;
#pragma unroll
        for (int w = 0; w < 8; w++) s += s_part[threadIdx.x][w];
        s_logit[threadIdx.x] = s;
    }
    __syncthreads();
    if (threadIdx.x == 0) {
        float lg[E_NUM];
#pragma unroll
        for (int e = 0; e < E_NUM; e++) lg[e] = s_logit[e];
        float mx = lg[0];
#pragma unroll
        for (int e = 1; e < E_NUM; e++) mx = fmaxf(mx, lg[e]);
        float pe[E_NUM], se = 0.f;
#pragma unroll
        for (int e = 0; e < E_NUM; e++) { pe[e] = expf(lg[e] - mx); se += pe[e]; }
#pragma unroll
        for (int e = 0; e < E_NUM; e++) pe[e] /= se;
        int b0 = 0;
#pragma unroll
        for (int e = 1; e < E_NUM; e++) if (pe[e] > pe[b0]) b0 = e;
        int b1 = -1;
#pragma unroll
        for (int e = 0; e < E_NUM; e++)
            if (e != b0 && (b1 < 0 || pe[e] > pe[b1])) b1 = e;
        float s2 = pe[b0] + pe[b1];
        int p0 = atomicAdd(&g_counts[b0], 1);
        g_tok [b0 * T_TOK + p0] = t; g_wgt[b0 * T_TOK + p0] = pe[b0] / s2;
        g_slot[b0 * T_TOK + p0] = 0;
        int p1 = atomicAdd(&g_counts[b1], 1);
        g_tok [b1 * T_TOK + p1] = t; g_wgt[b1 * T_TOK + p1] = pe[b1] / s2;
        g_slot[b1 * T_TOK + p1] = 1;
    }
}

// ---- split 8 float4 into fp16 hi/lo and store into buffer `bi` -------------
// hi chunks 0-3 (k 0..31), lo chunks 4-7, chunk idx ^= (row&7).
#define STS_SPLIT(bi, regs)                                                    \
    do {                                                                       \
        const uint32_t _rb = hbase + (uint32_t)(bi) * STAGE_B + row * 128u;    \
        uint32_t hreg[8], lreg[8];                                             \
        _Pragma("unroll")                                                      \
        for (int c = 0; c < 8; c++) {                                          \
            float4 v = (regs)[c];                                              \
            __half hx, lx, hy, ly, hz, lz, hw, lw;                             \
            split_f16(v.x, hx, lx); split_f16(v.y, hy, ly);                    \
            split_f16(v.z, hz, lz); split_f16(v.w, hw, lw);                    \
            hreg[c] = pack2(hx, hy) | 0u; lreg[c] = pack2(lx, ly) | 0u;        \
            /* pack 4 halves into 2 regs: (x,y) and (z,w) */                   \
            hreg[c] = pack2(hx, hy); lreg[c] = pack2(lx, ly);                  \
            /* second pair handled below via explicit arrays */                \
            (void)hz; (void)hw; (void)lz; (void)lw;                            \
            /* store both pairs in a temp layout */                            \
            hreg2[c] = pack2(hz, hw); lreg2[c] = pack2(lz, lw);                \
        }                                                                      \
        _Pragma("unroll")                                                      \
        for (int j = 0; j < 4; j++) {                                          \
            const uint32_t hoff = _rb + (uint32_t)(((j)     ^ (row & 7)) << 4);\
            const uint32_t loff = _rb + (uint32_t)(((4 + j) ^ (row & 7)) << 4);\
            asm volatile("st.shared.v4.b32 [%0], {%1,%2,%3,%4};"               \
                :: "r"(hoff), "r"(hreg[2*j]), "r"(hreg2[2*j]),                 \
                   "r"(hreg[2*j+1]), "r"(hreg2[2*j+1]) : "memory");            \
            asm volatile("st.shared.v4.b32 [%0], {%1,%2,%3,%4};"               \
                :: "r"(loff), "r"(lreg[2*j]), "r"(lreg2[2*j]),                 \
                   "r"(lreg[2*j+1]), "r"(lreg2[2*j+1]) : "memory");            \
        }                                                                      \
    } while (0)

// ======== 3xFP16 mainloop: 3-stage ring, 1 barrier/slab, k16 MMAs ===========
#define GEMM_MAINLOOP(SRC_PTR, KT)                                             \
    const int row = tid & 127;                                                 \
    const uint32_t hbase = tb + ((tid < 128) ? 0 : ATILE_B);                   \
    uint32_t hreg2[8], lreg2[8];                                               \
    float4 cur[8], nxt[8];                                                     \
    {   /* prologue: slab0 -> buf0, slab1 -> regs */                           \
        const float* s0 = (SRC_PTR);                                           \
        _Pragma("unroll")                                                      \
        for (int c = 0; c < 8; c++) cur[c] = *(const float4*)(s0 + c * 4);     \
        STS_SPLIT(0, cur);                                                     \
        const float* s1 = (SRC_PTR) + 32;                                      \
        _Pragma("unroll")                                                      \
        for (int c = 0; c < 8; c++) cur[c] = *(const float4*)(s1 + c * 4);     \
    }                                                                          \
    for (int k = 0; k < (KT); k++) {                                           \
        const int kb = k - (k / 3) * 3;          /* k % 3 */                   \
        if (k + 1 < (KT)) {                                                    \
            const int nb = (kb == 2) ? 0 : kb + 1;                             \
            STS_SPLIT(nb, cur);                                                \
        }                                                                      \
        if (k + 2 < (KT)) {                                                    \
            const float* sn = (SRC_PTR) + (k + 2) * 32;                        \
            _Pragma("unroll")                                                  \
            for (int c = 0; c < 8; c++) nxt[c] = *(const float4*)(sn + c * 4); \
        }                                                                      \
        __syncthreads();                                                       \
        const uint32_t Ab = tb + (uint32_t)kb * STAGE_B;                       \
        const uint32_t Bb = Ab + ATILE_B;                                      \
        _Pragma("unroll")                                                      \
        for (int s = 0; s < 2; s++) {   /* two k16 steps per 32-slab */        \
            uint32_t afh[4][4], afl[4][4], bfh[4][2], bfl[4][2];               \
            _Pragma("unroll")                                                  \
            for (int mt = 0; mt < 4; mt++) {                                   \
                const int ar = aRowB + mt * 16;                                \
                const uint32_t rb = Ab + (uint32_t)ar * 128u;                  \
                const uint32_t hc = (uint32_t)(((2*s + acs)     ^ (ar & 7)) << 4); \
                const uint32_t lc = (uint32_t)(((2*s + acs + 4) ^ (ar & 7)) << 4); \
                ldsm4(afh[mt], rb + hc);                                       \
                ldsm4(afl[mt], rb + lc);                                       \
            }                                                                  \
            _Pragma("unroll")                                                  \
            for (int p = 0; p < 2; p++) {                                      \
                const int br = bRowB + p * 16;                                 \
                const uint32_t rb = Bb + (uint32_t)br * 128u;                  \
                const uint32_t hc = (uint32_t)(((2*s + bcs)     ^ (br & 7)) << 4); \
                const uint32_t lc = (uint32_t)(((2*s + bcs + 4) ^ (br & 7)) << 4); \
                uint32_t rh[4], rl[4];                                         \
                ldsm4(rh, rb + hc);                                            \
                ldsm4(rl, rb + lc);                                            \
                bfh[2*p][0] = rh[0]; bfh[2*p][1] = rh[1];                      \
                bfh[2*p+1][0] = rh[2]; bfh[2*p+1][1] = rh[3];                  \
                bfl[2*p][0] = rl[0]; bfl[2*p][1] = rl[1];                      \
                bfl[2*p+1][0] = rl[2]; bfl[2*p+1][1] = rl[3];                  \
            }                                                                  \
            _Pragma("unroll")                                                  \
            for (int mt = 0; mt < 4; mt++)                                     \
                _Pragma("unroll")                                              \
                for (int nt = 0; nt < 4; nt++)                                 \
                    mma_f16(acc[mt][nt], afh[mt], bfl[nt]);                    \
            _Pragma("unroll")                                                  \
            for (int mt = 0; mt < 4; mt++)                                     \
                _Pragma("unroll")                                              \
                for (int nt = 0; nt < 4; nt++)                                 \
                    mma_f16(acc[mt][nt], afl[mt], bfh[nt]);                    \
            _Pragma("unroll")                                                  \
            for (int mt = 0; mt < 4; mt++)                                     \
                _Pragma("unroll")                                              \
                for (int nt = 0; nt < 4; nt++)                                 \
                    mma_f16(acc[mt][nt], afh[mt], bfh[nt]);                    \
        }                                                                      \
        _Pragma("unroll")                                                      \
        for (int c = 0; c < 8; c++) cur[c] = nxt[c];                           \
    }

// ---------------- GEMM1: gu[rows, 2816] = x[tok] * w1[e]^T  (K=2048) --------
__global__ __launch_bounds__(256, 1)
void gemm1_kernel(const float* __restrict__ x, const float* __restrict__ w1) {
    const int e    = blockIdx.z;
    const int rows = g_counts[e];
    const int m0   = blockIdx.x * 128;
    if (m0 >= rows) return;
    const int n0   = blockIdx.y * 128;

    extern __shared__ __align__(16) char smem[];
    const uint32_t sb = cvta_smem(smem);
    const uint32_t tb = (sb + 1023u) & ~1023u;
    const int tid = threadIdx.x, lane = tid & 31, wid = tid >> 5;
    const int wm = wid & 1, wn = wid >> 1;

    // fp16 ldmatrix fragment addressing:
    // A: row = wm*64 + mt*16 + ((grp&1)<<3) + r8, k-chunk sel = grp>>1
    // B: row = wn*32 + p*16 + ((grp>>1)<<3) + r8, k-chunk sel = grp&1
    const int grp = lane >> 3, r8 = lane & 7;
    const int acs = grp >> 1, bcs = grp & 1;
    const int aRowB = wm * 64 + ((grp & 1) << 3) + r8;
    const int bRowB = wn * 32 + ((grp >> 1) << 3) + r8;

    float acc[4][4][4];
#pragma unroll
    for (int i = 0; i < 4; i++)
#pragma unroll
        for (int j = 0; j < 4; j++)
#pragma unroll
            for (int q = 0; q < 4; q++) acc[i][j][q] = 0.f;

    const float* src;
    if (tid < 128) {
        const int mi = m0 + (tid & 127);
        const int tok = (mi < rows) ? g_tok[e * T_TOK + mi] : 0;
        src = x + (size_t)tok * H_DIM;
    } else {
        src = w1 + (size_t)e * GU_W * H_DIM + (size_t)(n0 + (tid & 127)) * H_DIM;
    }

    GEMM_MAINLOOP(src, (H_DIM / 32))

    const int lr = lane >> 2, lc = (lane & 3) * 2;
    const int mb = m0 + wm * 64, nb = n0 + wn * 32;
#pragma unroll
    for (int mt = 0; mt < 4; mt++) {
#pragma unroll
        for (int half = 0; half < 2; half++) {
            const int orow = mb + mt * 16 + half * 8 + lr;
            if (orow < rows) {
                float* dst = g_gu + (size_t)(e * T_TOK + orow) * GU_W + nb + lc;
#pragma unroll
                for (int nt = 0; nt < 4; nt++) {
                    float2 v = make_float2(acc[mt][nt][2 * half], acc[mt][nt][2 * half + 1]);
                    *(float2*)(dst + nt * 8) = v;
                }
            }
        }
    }
}

// ---------------- kernel 3: act = silu(g) * u (in place) --------------------
__global__ void act_kernel() {
    const int r = blockIdx.x;
    const int e = r / T_TOK, pos = r % T_TOK;
    if (pos >= g_counts[e]) return;
    float* gu = g_gu + (size_t)r * GU_W;
    for (int i = threadIdx.x * 4; i < I_DIM; i += blockDim.x * 4) {
        float4 g4 = *(const float4*)(gu + i);
        float4 u4 = *(const float4*)(gu + I_DIM + i);
        float4 o;
        o.x = (g4.x / (1.f + expf(-g4.x))) * u4.x;
        o.y = (g4.y / (1.f + expf(-g4.y))) * u4.y;
        o.z = (g4.z / (1.f + expf(-g4.z))) * u4.z;
        o.w = (g4.w / (1.f + expf(-g4.w))) * u4.w;
        *(float4*)(gu + i) = o;
    }
}

// ---------------- GEMM2: slot_out = wgt * (act * w2[e]^T)  (K=1408) ---------
__global__ __launch_bounds__(256, 1)
void gemm2_kernel(const float* __restrict__ w2) {
    const int e    = blockIdx.z;
    const int rows = g_counts[e];
    const int m0   = blockIdx.x * 128;
    if (m0 >= rows) return;
    const int n0   = blockIdx.y * 128;

    extern __shared__ __align__(16) char smem[];
    const uint32_t sb = cvta_smem(smem);
    const uint32_t tb = (sb + 1023u) & ~1023u;
    const int tid = threadIdx.x, lane = tid & 31, wid = tid >> 5;
    const int wm = wid & 1, wn = wid >> 1;

    const int grp = lane >> 3, r8 = lane & 7;
    const int acs = grp >> 1, bcs = grp & 1;
    const int aRowB = wm * 64 + ((grp & 1) << 3) + r8;
    const int bRowB = wn * 32 + ((grp >> 1) << 3) + r8;

    float acc[4][4][4];
#pragma unroll
    for (int i = 0; i < 4; i++)
#pragma unroll
        for (int j = 0; j < 4; j++)
#pragma unroll
            for (int q = 0; q < 4; q++) acc[i][j][q] = 0.f;

    const float* src;
    if (tid < 128) {
        const int mi = m0 + (tid & 127);
        const int rr = (mi < rows) ? mi : 0;
        src = g_gu + (size_t)(e * T_TOK + rr) * GU_W;
    } else {
        src = w2 + (size_t)e * H_DIM * I_DIM + (size_t)(n0 + (tid & 127)) * I_DIM;
    }

    GEMM_MAINLOOP(src, (I_DIM / 32))

    const int lr = lane >> 2, lc = (lane & 3) * 2;
    const int mb = m0 + wm * 64, nbase = n0 + wn * 32;
#pragma unroll
    for (int mt = 0; mt < 4; mt++) {
#pragma unroll
        for (int half = 0; half < 2; half++) {
            const int orow = mb + mt * 16 + half * 8 + lr;
            if (orow < rows) {
                const int li = e * T_TOK + orow;
                const float w = g_wgt[li];
                const int tok = g_tok[li];
                const int slot = g_slot[li];
                float* dst = g_slotout + (size_t)slot * T_TOK * H_DIM
                                       + (size_t)tok * H_DIM + nbase + lc;
#pragma unroll
                for (int nt = 0; nt < 4; nt++) {
                    float2 v = make_float2(w * acc[mt][nt][2 * half],
                                           w * acc[mt][nt][2 * half + 1]);
                    *(float2*)(dst + nt * 8) = v;
                }
            }
        }
    }
}

// ---------------- kernel 5: combine slot0 + slot1 -> out --------------------
__global__ void combine_kernel(float* __restrict__ out) {
    const size_t idx4 = (size_t)blockIdx.x * blockDim.x + threadIdx.x;
    const size_t n4   = (size_t)T_TOK * H_DIM / 4;
    if (idx4 >= n4) return;
    float4 a = *((const float4*)g_slotout + idx4);
    float4 b = *((const float4*)g_slotout + n4 + idx4);
    float4 r; r.x = a.x + b.x; r.y = a.y + b.y; r.z = a.z + b.z; r.w = a.w + b.w;
    *((float4*)out + idx4) = r;
}

// ---------------- launch ----------------------------------------------------
extern "C" void kernel_launch(void* const* d_in, const int* in_sizes, int n_in,
                              void* d_out, int out_size) {
    const float* x  = (const float*)d_in[0];
    const float* gw = (const float*)d_in[1];
    const float* w1 = (const float*)d_in[2];
    const float* w2 = (const float*)d_in[3];
    float* out = (float*)d_out;

    cudaFuncSetAttribute(gemm1_kernel, cudaFuncAttributeMaxDynamicSharedMemorySize, SMEM_DYN);
    cudaFuncSetAttribute(gemm2_kernel, cudaFuncAttributeMaxDynamicSharedMemorySize, SMEM_DYN);

    zero_counts_kernel<<<1, 32>>>();
    gate_kernel<<<T_TOK, 256>>>(x, gw);

    dim3 g1(T_TOK / 128, GU_W / 128, E_NUM);   // (16, 22, 8)
    gemm1_kernel<<<g1, 256, SMEM_DYN>>>(x, w1);

    act_kernel<<<E_NUM * T_TOK, 128>>>();

    dim3 g2(T_TOK / 128, H_DIM / 128, E_NUM);  // (16, 16, 8)
    gemm2_kernel<<<g2, 256, SMEM_DYN>>>(w2);

    combine_kernel<<<(T_TOK * H_DIM / 4 + 255) / 256, 256>>>(out);
}

// round 15
// speedup vs baseline: 1.7132x; 1.1121x over previous
#include <cuda_runtime.h>
#include <cuda_fp16.h>
#include <math.h>
#include <stdint.h>

// Problem constants (B=2, S=1024, H=2048, I=1408, E=8, TOP_K=2)
#define T_TOK 2048
#define H_DIM 2048
#define I_DIM 1408
#define E_NUM 8
#define GU_W  (2*I_DIM)   // 2816

// ---------------- scratch (device globals; no allocations allowed) ----------
__device__ int   g_counts[E_NUM];
__device__ int   g_tok [E_NUM*T_TOK];
__device__ float g_wgt [E_NUM*T_TOK];
__device__ int   g_slot[E_NUM*T_TOK];
__device__ __align__(16) float g_gu[(size_t)E_NUM*T_TOK*GU_W];        // ~184 MB
__device__ __align__(16) float g_slotout[2ull*T_TOK*H_DIM];           // ~33 MB

// ---------------- PTX helpers ----------------------------------------------
__device__ __forceinline__ uint32_t cvta_smem(const void* p) {
    uint32_t r;
    asm("{ .reg .u64 t; cvta.to.shared.u64 t, %1; cvt.u32.u64 %0, t; }"
        : "=r"(r) : "l"(p));
    return r;
}
__device__ __forceinline__ void ldsm4(uint32_t* r, uint32_t addr) {
    asm volatile("ldmatrix.sync.aligned.m8n8.x4.shared.b16 {%0,%1,%2,%3}, [%4];"
        : "=r"(r[0]), "=r"(r[1]), "=r"(r[2]), "=r"(r[3]) : "r"(addr));
}
// fp16 MMA m16n8k16, fp32 accumulate
__device__ __forceinline__ void mma_f16(float* c, const uint32_t* a, const uint32_t* b) {
    asm volatile(
        "mma.sync.aligned.m16n8k16.row.col.f32.f16.f16.f32 "
        "{%0,%1,%2,%3}, {%4,%5,%6,%7}, {%8,%9}, {%0,%1,%2,%3};"
        : "+f"(c[0]), "+f"(c[1]), "+f"(c[2]), "+f"(c[3])
        : "r"(a[0]), "r"(a[1]), "r"(a[2]), "r"(a[3]), "r"(b[0]), "r"(b[1]));
}
__device__ __forceinline__ void split_f16(float v, __half& hi, __half& lo) {
    hi = __float2half_rn(v);
    lo = __float2half_rn(v - __half2float(hi));
}
__device__ __forceinline__ uint32_t pack2(__half a, __half b) {
    __half2 h = __halves2half2(a, b);
    return *(uint32_t*)&h;
}

// smem: 3-stage ring; each stage 32KB = A(16K: hi rows, lo half unused) + B(16K hi|lo)
// Row layout: 128 bytes = 8 chunks of 16B; chunk j (0-3) = hi fp16 k=8j..8j+7,
// chunk 4+j = lo. Chunk index swizzled: c ^= (row & 7). A-side stores hi only.
#define ATILE_B  16384
#define STAGE_B  32768
#define SMEM_DYN (1024 + 3*STAGE_B)   // ~97KB

// ---------------- kernel 0: zero counters ----------------------------------
__global__ void zero_counts_kernel() {
    if (threadIdx.x < E_NUM) g_counts[threadIdx.x] = 0;
}

// ---------------- kernel 1: gating ------------------------------------------
__global__ void gate_kernel(const float* __restrict__ x,
                            const float* __restrict__ gw) {
    const int t = blockIdx.x;
    const float* xr = x + (size_t)t * H_DIM;
    float acc[E_NUM];
#pragma unroll
    for (int e = 0; e < E_NUM; e++) acc[e] = 0.f;
    for (int h = threadIdx.x; h < H_DIM; h += blockDim.x) {
        float xv = xr[h];
#pragma unroll
        for (int e = 0; e < E_NUM; e++) acc[e] += xv * gw[e * H_DIM + h];
    }
    __shared__ float s_part[E_NUM][8];
    __shared__ float s_logit[E_NUM];
    const int lane = threadIdx.x & 31, warp = threadIdx.x >> 5;
#pragma unroll
    for (int off = 16; off > 0; off >>= 1)
#pragma unroll
        for (int e = 0; e < E_NUM; e++)
            acc[e] += __shfl_down_sync(0xffffffffu, acc[e], off);
    if (lane == 0)
#pragma unroll
        for (int e = 0; e < E_NUM; e++) s_part[e][warp] = acc[e];
    __syncthreads();
    if (threadIdx.x < E_NUM) {
        float s = 0.f;
#pragma unroll
        for (int w = 0; w < 8; w++) s += s_part[threadIdx.x][w];
        s_logit[threadIdx.x] = s;
    }
    __syncthreads();
    if (threadIdx.x == 0) {
        float lg[E_NUM];
#pragma unroll
        for (int e = 0; e < E_NUM; e++) lg[e] = s_logit[e];
        float mx = lg[0];
#pragma unroll
        for (int e = 1; e < E_NUM; e++) mx = fmaxf(mx, lg[e]);
        float pe[E_NUM], se = 0.f;
#pragma unroll
        for (int e = 0; e < E_NUM; e++) { pe[e] = expf(lg[e] - mx); se += pe[e]; }
#pragma unroll
        for (int e = 0; e < E_NUM; e++) pe[e] /= se;
        int b0 = 0;
#pragma unroll
        for (int e = 1; e < E_NUM; e++) if (pe[e] > pe[b0]) b0 = e;
        int b1 = -1;
#pragma unroll
        for (int e = 0; e < E_NUM; e++)
            if (e != b0 && (b1 < 0 || pe[e] > pe[b1])) b1 = e;
        float s2 = pe[b0] + pe[b1];
        int p0 = atomicAdd(&g_counts[b0], 1);
        g_tok [b0 * T_TOK + p0] = t; g_wgt[b0 * T_TOK + p0] = pe[b0] / s2;
        g_slot[b0 * T_TOK + p0] = 0;
        int p1 = atomicAdd(&g_counts[b1], 1);
        g_tok [b1 * T_TOK + p1] = t; g_wgt[b1 * T_TOK + p1] = pe[b1] / s2;
        g_slot[b1 * T_TOK + p1] = 1;
    }
}

// ---- split 8 float4 and store into buffer `bi`.
// A rows (is_a): hi only. B rows: hi + lo.
#define STS_SPLIT(bi, regs)                                                    \
    do {                                                                       \
        const uint32_t _rb = hbase + (uint32_t)(bi) * STAGE_B + row * 128u;    \
        uint32_t h1[8], h2[8], l1[8], l2[8];                                   \
        _Pragma("unroll")                                                      \
        for (int c = 0; c < 8; c++) {                                          \
            float4 v = (regs)[c];                                              \
            __half hx, lx, hy, ly, hz, lz, hw, lw;                             \
            split_f16(v.x, hx, lx); split_f16(v.y, hy, ly);                    \
            split_f16(v.z, hz, lz); split_f16(v.w, hw, lw);                    \
            h1[c] = pack2(hx, hy); h2[c] = pack2(hz, hw);                      \
            l1[c] = pack2(lx, ly); l2[c] = pack2(lz, lw);                      \
        }                                                                      \
        _Pragma("unroll")                                                      \
        for (int j = 0; j < 4; j++) {                                          \
            const uint32_t hoff = _rb + (uint32_t)(((j)     ^ (row & 7)) << 4);\
            asm volatile("st.shared.v4.b32 [%0], {%1,%2,%3,%4};"               \
                :: "r"(hoff), "r"(h1[2*j]), "r"(h2[2*j]),                      \
                   "r"(h1[2*j+1]), "r"(h2[2*j+1]) : "memory");                 \
        }                                                                      \
        if (!is_a) {                                                           \
            _Pragma("unroll")                                                  \
            for (int j = 0; j < 4; j++) {                                      \
                const uint32_t loff = _rb + (uint32_t)(((4+j) ^ (row & 7)) << 4);\
                asm volatile("st.shared.v4.b32 [%0], {%1,%2,%3,%4};"           \
                    :: "r"(loff), "r"(l1[2*j]), "r"(l2[2*j]),                  \
                       "r"(l1[2*j+1]), "r"(l2[2*j+1]) : "memory");             \
            }                                                                  \
        }                                                                      \
    } while (0)

// ======== 2-term FP16 mainloop (ah*bh + ah*bl): 3-stage ring ================
#define GEMM_MAINLOOP(SRC_PTR, KT)                                             \
    const int row = tid & 127;                                                 \
    const bool is_a = (tid < 128);                                             \
    const uint32_t hbase = tb + (is_a ? 0 : ATILE_B);                          \
    float4 cur[8], nxt[8];                                                     \
    {   /* prologue: slab0 -> buf0, slab1 -> regs */                           \
        const float* s0 = (SRC_PTR);                                           \
        _Pragma("unroll")                                                      \
        for (int c = 0; c < 8; c++) cur[c] = *(const float4*)(s0 + c * 4);     \
        STS_SPLIT(0, cur);                                                     \
        const float* s1 = (SRC_PTR) + 32;                                      \
        _Pragma("unroll")                                                      \
        for (int c = 0; c < 8; c++) cur[c] = *(const float4*)(s1 + c * 4);     \
    }                                                                          \
    for (int k = 0; k < (KT); k++) {                                           \
        const int kb = k - (k / 3) * 3;          /* k % 3 */                   \
        if (k + 1 < (KT)) {                                                    \
            const int nb = (kb == 2) ? 0 : kb + 1;                             \
            STS_SPLIT(nb, cur);                                                \
        }                                                                      \
        if (k + 2 < (KT)) {                                                    \
            const float* sn = (SRC_PTR) + (k + 2) * 32;                        \
            _Pragma("unroll")                                                  \
            for (int c = 0; c < 8; c++) nxt[c] = *(const float4*)(sn + c * 4); \
        }                                                                      \
        __syncthreads();                                                       \
        const uint32_t Ab = tb + (uint32_t)kb * STAGE_B;                       \
        const uint32_t Bb = Ab + ATILE_B;                                      \
        _Pragma("unroll")                                                      \
        for (int s = 0; s < 2; s++) {   /* two k16 steps per 32-slab */        \
            uint32_t afh[4][4], bfh[4][2], bfl[4][2];                          \
            _Pragma("unroll")                                                  \
            for (int mt = 0; mt < 4; mt++) {                                   \
                const int ar = aRowB + mt * 16;                                \
                const uint32_t rb = Ab + (uint32_t)ar * 128u;                  \
                const uint32_t hc = (uint32_t)(((2*s + acs) ^ (ar & 7)) << 4); \
                ldsm4(afh[mt], rb + hc);                                       \
            }                                                                  \
            _Pragma("unroll")                                                  \
            for (int p = 0; p < 2; p++) {                                      \
                const int br = bRowB + p * 16;                                 \
                const uint32_t rb = Bb + (uint32_t)br * 128u;                  \
                const uint32_t hc = (uint32_t)(((2*s + bcs)     ^ (br & 7)) << 4); \
                const uint32_t lc = (uint32_t)(((2*s + bcs + 4) ^ (br & 7)) << 4); \
                uint32_t rh[4], rl[4];                                         \
                ldsm4(rh, rb + hc);                                            \
                ldsm4(rl, rb + lc);                                            \
                bfh[2*p][0] = rh[0]; bfh[2*p][1] = rh[1];                      \
                bfh[2*p+1][0] = rh[2]; bfh[2*p+1][1] = rh[3];                  \
                bfl[2*p][0] = rl[0]; bfl[2*p][1] = rl[1];                      \
                bfl[2*p+1][0] = rl[2]; bfl[2*p+1][1] = rl[3];                  \
            }                                                                  \
            /* sweep 1: ah*bl (16 independent) */                              \
            _Pragma("unroll")                                                  \
            for (int mt = 0; mt < 4; mt++)                                     \
                _Pragma("unroll")                                              \
                for (int nt = 0; nt < 4; nt++)                                 \
                    mma_f16(acc[mt][nt], afh[mt], bfl[nt]);                    \
            /* sweep 2: ah*bh */                                               \
            _Pragma("unroll")                                                  \
            for (int mt = 0; mt < 4; mt++)                                     \
                _Pragma("unroll")                                              \
                for (int nt = 0; nt < 4; nt++)                                 \
                    mma_f16(acc[mt][nt], afh[mt], bfh[nt]);                    \
        }                                                                      \
        _Pragma("unroll")                                                      \
        for (int c = 0; c < 8; c++) cur[c] = nxt[c];                           \
    }

// ---------------- GEMM1: gu[rows, 2816] = x[tok] * w1[e]^T  (K=2048) --------
__global__ __launch_bounds__(256, 1)
void gemm1_kernel(const float* __restrict__ x, const float* __restrict__ w1) {
    const int e    = blockIdx.z;
    const int rows = g_counts[e];
    const int m0   = blockIdx.x * 128;
    if (m0 >= rows) return;
    const int n0   = blockIdx.y * 128;

    extern __shared__ __align__(16) char smem[];
    const uint32_t sb = cvta_smem(smem);
    const uint32_t tb = (sb + 1023u) & ~1023u;
    const int tid = threadIdx.x, lane = tid & 31, wid = tid >> 5;
    const int wm = wid & 1, wn = wid >> 1;

    const int grp = lane >> 3, r8 = lane & 7;
    const int acs = grp >> 1, bcs = grp & 1;
    const int aRowB = wm * 64 + ((grp & 1) << 3) + r8;
    const int bRowB = wn * 32 + ((grp >> 1) << 3) + r8;

    float acc[4][4][4];
#pragma unroll
    for (int i = 0; i < 4; i++)
#pragma unroll
        for (int j = 0; j < 4; j++)
#pragma unroll
            for (int q = 0; q < 4; q++) acc[i][j][q] = 0.f;

    const float* src;
    if (tid < 128) {
        const int mi = m0 + (tid & 127);
        const int tok = (mi < rows) ? g_tok[e * T_TOK + mi] : 0;
        src = x + (size_t)tok * H_DIM;
    } else {
        src = w1 + (size_t)e * GU_W * H_DIM + (size_t)(n0 + (tid & 127)) * H_DIM;
    }

    GEMM_MAINLOOP(src, (H_DIM / 32))

    const int lr = lane >> 2, lc = (lane & 3) * 2;
    const int mb = m0 + wm * 64, nb = n0 + wn * 32;
#pragma unroll
    for (int mt = 0; mt < 4; mt++) {
#pragma unroll
        for (int half = 0; half < 2; half++) {
            const int orow = mb + mt * 16 + half * 8 + lr;
            if (orow < rows) {
                float* dst = g_gu + (size_t)(e * T_TOK + orow) * GU_W + nb + lc;
#pragma unroll
                for (int nt = 0; nt < 4; nt++) {
                    float2 v = make_float2(acc[mt][nt][2 * half], acc[mt][nt][2 * half + 1]);
                    *(float2*)(dst + nt * 8) = v;
                }
            }
        }
    }
}

// ---------------- kernel 3: act = silu(g) * u (in place) --------------------
__global__ void act_kernel() {
    const int r = blockIdx.x;
    const int e = r / T_TOK, pos = r % T_TOK;
    if (pos >= g_counts[e]) return;
    float* gu = g_gu + (size_t)r * GU_W;
    for (int i = threadIdx.x * 4; i < I_DIM; i += blockDim.x * 4) {
        float4 g4 = *(const float4*)(gu + i);
        float4 u4 = *(const float4*)(gu + I_DIM + i);
        float4 o;
        o.x = (g4.x / (1.f + expf(-g4.x))) * u4.x;
        o.y = (g4.y / (1.f + expf(-g4.y))) * u4.y;
        o.z = (g4.z / (1.f + expf(-g4.z))) * u4.z;
        o.w = (g4.w / (1.f + expf(-g4.w))) * u4.w;
        *(float4*)(gu + i) = o;
    }
}

// ---------------- GEMM2: slot_out = wgt * (act * w2[e]^T)  (K=1408) ---------
__global__ __launch_bounds__(256, 1)
void gemm2_kernel(const float* __restrict__ w2) {
    const int e    = blockIdx.z;
    const int rows = g_counts[e];
    const int m0   = blockIdx.x * 128;
    if (m0 >= rows) return;
    const int n0   = blockIdx.y * 128;

    extern __shared__ __align__(16) char smem[];
    const uint32_t sb = cvta_smem(smem);
    const uint32_t tb = (sb + 1023u) & ~1023u;
    const int tid = threadIdx.x, lane = tid & 31, wid = tid >> 5;
    const int wm = wid & 1, wn = wid >> 1;

    const int grp = lane >> 3, r8 = lane & 7;
    const int acs = grp >> 1, bcs = grp & 1;
    const int aRowB = wm * 64 + ((grp & 1) << 3) + r8;
    const int bRowB = wn * 32 + ((grp >> 1) << 3) + r8;

    float acc[4][4][4];
#pragma unroll
    for (int i = 0; i < 4; i++)
#pragma unroll
        for (int j = 0; j < 4; j++)
#pragma unroll
            for (int q = 0; q < 4; q++) acc[i][j][q] = 0.f;

    const float* src;
    if (tid < 128) {
        const int mi = m0 + (tid & 127);
        const int rr = (mi < rows) ? mi : 0;
        src = g_gu + (size_t)(e * T_TOK + rr) * GU_W;
    } else {
        src = w2 + (size_t)e * H_DIM * I_DIM + (size_t)(n0 + (tid & 127)) * I_DIM;
    }

    GEMM_MAINLOOP(src, (I_DIM / 32))

    const int lr = lane >> 2, lc = (lane & 3) * 2;
    const int mb = m0 + wm * 64, nbase = n0 + wn * 32;
#pragma unroll
    for (int mt = 0; mt < 4; mt++) {
#pragma unroll
        for (int half = 0; half < 2; half++) {
            const int orow = mb + mt * 16 + half * 8 + lr;
            if (orow < rows) {
                const int li = e * T_TOK + orow;
                const float w = g_wgt[li];
                const int tok = g_tok[li];
                const int slot = g_slot[li];
                float* dst = g_slotout + (size_t)slot * T_TOK * H_DIM
                                       + (size_t)tok * H_DIM + nbase + lc;
#pragma unroll
                for (int nt = 0; nt < 4; nt++) {
                    float2 v = make_float2(w * acc[mt][nt][2 * half],
                                           w * acc[mt][nt][2 * half + 1]);
                    *(float2*)(dst + nt * 8) = v;
                }
            }
        }
    }
}

// ---------------- kernel 5: combine slot0 + slot1 -> out --------------------
__global__ void combine_kernel(float* __restrict__ out) {
    const size_t idx4 = (size_t)blockIdx.x * blockDim.x + threadIdx.x;
    const size_t n4   = (size_t)T_TOK * H_DIM / 4;
    if (idx4 >= n4) return;
    float4 a = *((const float4*)g_slotout + idx4);
    float4 b = *((const float4*)g_slotout + n4 + idx4);
    float4 r; r.x = a.x + b.x; r.y = a.y + b.y; r.z = a.z + b.z; r.w = a.w + b.w;
    *((float4*)out + idx4) = r;
}

// ---------------- launch ----------------------------------------------------
extern "C" void kernel_launch(void* const* d_in, const int* in_sizes, int n_in,
                              void* d_out, int out_size) {
    const float* x  = (const float*)d_in[0];
    const float* gw = (const float*)d_in[1];
    const float* w1 = (const float*)d_in[2];
    const float* w2 = (const float*)d_in[3];
    float* out = (float*)d_out;

    cudaFuncSetAttribute(gemm1_kernel, cudaFuncAttributeMaxDynamicSharedMemorySize, SMEM_DYN);
    cudaFuncSetAttribute(gemm2_kernel, cudaFuncAttributeMaxDynamicSharedMemorySize, SMEM_DYN);

    zero_counts_kernel<<<1, 32>>>();
    gate_kernel<<<T_TOK, 256>>>(x, gw);

    dim3 g1(T_TOK / 128, GU_W / 128, E_NUM);   // (16, 22, 8)
    gemm1_kernel<<<g1, 256, SMEM_DYN>>>(x, w1);

    act_kernel<<<E_NUM * T_TOK, 128>>>();

    dim3 g2(T_TOK / 128, H_DIM / 128, E_NUM);  // (16, 16, 8)
    gemm2_kernel<<<g2, 256, SMEM_DYN>>>(w2);

    combine_kernel<<<(T_TOK * H_DIM / 4 + 255) / 256, 256>>>(out);
}